// round 12
// baseline (speedup 1.0000x reference)
#include <cuda_runtime.h>
#include <cuda_fp16.h>
#include <math.h>

#define NMAX 100000
#define EMAX 1600000
#define CSRMAX (EMAX + 8 * NMAX)     // padded CSR capacity (pad to multiple of 8)
#define EPS 1e-5f
#define SCAN_BLK 1024
#define MAX_BLKS 128                 // ceil(100000/1024)=98 <= 128

// ---- device scratch (no allocations allowed). All zero at module load. ----
__device__ int      g_deg [NMAX];        // re-zeroed by k_pad_zero each launch
__device__ int      g_off [NMAX + 1];
__device__ unsigned g_state[MAX_BLKS];   // re-zeroed by k_pad_zero each launch
__device__ float    g_dinv[NMAX];
__device__ int      g_rank[EMAX];        // within-row rank of each edge
__device__ int      g_csr [CSRMAX];      // real slots by k_build, padding by k_pad_zero
__device__ __half   g_h   [(size_t)(NMAX + 1) * 64];  // gemm outputs; row NMAX never written => 0
__device__ __half   g_hb  [(size_t)(NMAX + 1) * 64];  // pull outputs; row NMAX never written => 0

// ---------- count + rank: one atomic pass; rank[e] = old degree ----------
__global__ void k_count(const int* __restrict__ row, int E) {
    int t = blockIdx.x * blockDim.x + threadIdx.x;
    int stride = gridDim.x * blockDim.x;
    #pragma unroll
    for (int j = 0; j < 4; j++) {
        int e = t + j * stride;
        if (e < E) g_rank[e] = atomicAdd(&g_deg[row[e]], 1);
    }
}

// ---------- decoupled-lookback scan (warp-parallel lookback) + dinv ----------
__global__ __launch_bounds__(SCAN_BLK)
void k_scan_lb(int N) {
    __shared__ int warp_sums[32];
    __shared__ int s_prefix;

    int bid  = blockIdx.x;
    int tid  = threadIdx.x;
    int lane = tid & 31;
    int wid  = tid >> 5;
    int i    = bid * SCAN_BLK + tid;

    int v = (i < N) ? g_deg[i] : 0;
    if (i < N) g_dinv[i] = rsqrtf((float)v + 1.0f);   // +1 = self loop
    int vp = (v + 7) & ~7;                            // pad degree to multiple of 8

    int x = vp;
    #pragma unroll
    for (int d = 1; d < 32; d <<= 1) {
        int t = __shfl_up_sync(0xFFFFFFFFu, x, d);
        if (lane >= d) x += t;
    }
    if (lane == 31) warp_sums[wid] = x;
    __syncthreads();
    if (wid == 0) {
        int y = warp_sums[lane];
        #pragma unroll
        for (int d = 1; d < 32; d <<= 1) {
            int t = __shfl_up_sync(0xFFFFFFFFu, y, d);
            if (lane >= d) y += t;
        }
        warp_sums[lane] = y;
    }
    __syncthreads();

    int block_incl  = x + (wid > 0 ? warp_sums[wid - 1] : 0);
    int block_total = warp_sums[31];

    if (wid == 0) {
        if (bid == 0) {
            if (lane == 0) {
                s_prefix = 0;
                atomicExch(&g_state[0], (2u << 28) | (unsigned)block_total);
            }
        } else {
            if (lane == 0)
                atomicExch(&g_state[bid], (1u << 28) | (unsigned)block_total);
            int run = 0;
            int j0 = bid - 1;
            while (true) {
                int idx = j0 - lane;
                unsigned st = (idx >= 0) ? atomicAdd(&g_state[idx], 0u) : (2u << 28);
                if (__any_sync(0xFFFFFFFFu, (st >> 28) == 0u)) { __nanosleep(20); continue; }
                unsigned pm = __ballot_sync(0xFFFFFFFFu, (st >> 28) == 2u);
                if (pm) {
                    int L = __ffs((int)pm) - 1;
                    int val = (lane <= L) ? (int)(st & 0x0FFFFFFFu) : 0;
                    run += __reduce_add_sync(0xFFFFFFFFu, val);
                    break;
                } else {
                    run += __reduce_add_sync(0xFFFFFFFFu, (int)(st & 0x0FFFFFFFu));
                    j0 -= 32;
                }
            }
            if (lane == 0) {
                s_prefix = run;
                atomicExch(&g_state[bid], (2u << 28) | (unsigned)(run + block_total));
            }
        }
    }
    __syncthreads();

    if (tid == 0 && bid == (int)gridDim.x - 1)
        g_off[N] = s_prefix + block_total;

    int ex = s_prefix + block_incl - vp;              // exclusive prefix (8-aligned)
    if (i < N) g_off[i] = ex;
}

// ---------- pad padding slots + zero deg/state for the NEXT launch ----------
__global__ void k_pad_zero(int N) {
    int i = blockIdx.x * blockDim.x + threadIdx.x;
    if (i < MAX_BLKS) g_state[i] = 0;
    if (i >= N) return;
    int d = g_deg[i];
    int p = g_off[i] + d;
    int e = g_off[i] + ((d + 7) & ~7);
    for (; p < e; p++) g_csr[p] = NMAX;
    g_deg[i] = 0;
}

// ---------- scatter real edges: NO atomics, 8 chains/thread ----------
__global__ void k_build(const int* __restrict__ row, const int* __restrict__ col, int E) {
    int t = blockIdx.x * blockDim.x + threadIdx.x;
    int stride = gridDim.x * blockDim.x;
    #pragma unroll
    for (int j = 0; j < 8; j++) {
        int e = t + j * stride;
        if (e < E) {
            int pos = __ldg(&g_off[row[e]]) + g_rank[e];
            g_csr[pos] = col[e];
        }
    }
}

// ---------- scale: h[i,:] *= dinv[i] (fp32 math, fp16 storage) ----------
__global__ void k_scale(__half* __restrict__ h, int N) {
    int idx = blockIdx.x * blockDim.x + threadIdx.x;
    if (idx >= N * 16) return;
    int i = idx >> 4;
    float di = g_dinv[i];
    uint2* h2 = reinterpret_cast<uint2*>(h);
    uint2 v = h2[idx];
    float2 f0 = __half22float2(*reinterpret_cast<__half2*>(&v.x));
    float2 f1 = __half22float2(*reinterpret_cast<__half2*>(&v.y));
    __half2 r0 = __floats2half2_rn(f0.x * di, f0.y * di);
    __half2 r1 = __floats2half2_rn(f1.x * di, f1.y * di);
    uint2 st;
    st.x = *reinterpret_cast<unsigned*>(&r0);
    st.y = *reinterpret_cast<unsigned*>(&r1);
    h2[idx] = st;
}

// ------------------- GEMM (fp32 input, NO dinv scale): layer-1 early start ----------
#define GEMM_ROWS 64

__global__ __launch_bounds__(256)
void k_gemm_f32(const float* __restrict__ in, const float* __restrict__ W,
                __half* __restrict__ out, int N)
{
    __shared__ float Wt[64][66];
    __shared__ float Xs[GEMM_ROWS][64];

    int tid = threadIdx.x;
    int row0 = blockIdx.x * GEMM_ROWS;

    #pragma unroll
    for (int i = tid; i < 64 * 64; i += 256) {
        int k = i >> 6, c = i & 63;
        Wt[c][k] = W[i];
    }
    #pragma unroll
    for (int i = tid; i < GEMM_ROWS * 16; i += 256) {
        int r = i >> 4, k4 = (i & 15);
        int gr = row0 + r;
        float4 v = (gr < N) ? reinterpret_cast<const float4*>(in)[(size_t)gr * 16 + k4]
                            : make_float4(0.f, 0.f, 0.f, 0.f);
        reinterpret_cast<float4*>(&Xs[r][0])[k4] = v;
    }
    __syncthreads();

    int cg = tid & 15;
    int rg = tid >> 4;
    int r0 = rg * 4;

    unsigned long long acc[4][4];
    #pragma unroll
    for (int a = 0; a < 4; a++)
        #pragma unroll
        for (int b = 0; b < 4; b++)
            acc[a][b] = 0ULL;

    #pragma unroll 8
    for (int kp = 0; kp < 32; kp++) {
        unsigned long long xv[4], wv[4];
        #pragma unroll
        for (int a = 0; a < 4; a++)
            xv[a] = *reinterpret_cast<const unsigned long long*>(&Xs[r0 + a][kp * 2]);
        #pragma unroll
        for (int b = 0; b < 4; b++)
            wv[b] = *reinterpret_cast<const unsigned long long*>(&Wt[cg + 16 * b][kp * 2]);
        #pragma unroll
        for (int a = 0; a < 4; a++)
            #pragma unroll
            for (int b = 0; b < 4; b++)
                asm("fma.rn.f32x2 %0, %1, %2, %0;"
                    : "+l"(acc[a][b]) : "l"(xv[a]), "l"(wv[b]));
    }

    #pragma unroll
    for (int a = 0; a < 4; a++) {
        int gr = row0 + r0 + a;
        if (gr < N) {
            #pragma unroll
            for (int b = 0; b < 4; b++) {
                float lo, hi;
                asm("mov.b64 {%0,%1}, %2;" : "=f"(lo), "=f"(hi) : "l"(acc[a][b]));
                out[(size_t)gr * 64 + cg + 16 * b] = __float2half_rn(lo + hi);
            }
        }
    }
}

// ------------------- GEMM (fp16 input, dinv-scaled fp16 out), ranged [n0,n1) ----------
__global__ __launch_bounds__(256)
void k_gemm_f16(const __half* __restrict__ in, const float* __restrict__ W,
                __half* __restrict__ out, int n0, int n1)
{
    __shared__ float Wt[64][66];
    __shared__ float Xs[GEMM_ROWS][64];

    int tid = threadIdx.x;
    int row0 = n0 + blockIdx.x * GEMM_ROWS;

    #pragma unroll
    for (int i = tid; i < 64 * 64; i += 256) {
        int k = i >> 6, c = i & 63;
        Wt[c][k] = W[i];
    }
    #pragma unroll
    for (int i = tid; i < GEMM_ROWS * 16; i += 256) {
        int r = i >> 4, k4 = (i & 15);
        int gr = row0 + r;
        uint2 v = (gr < n1) ? reinterpret_cast<const uint2*>(in)[(size_t)gr * 16 + k4]
                            : make_uint2(0u, 0u);
        float2 f0 = __half22float2(*reinterpret_cast<__half2*>(&v.x));
        float2 f1 = __half22float2(*reinterpret_cast<__half2*>(&v.y));
        reinterpret_cast<float4*>(&Xs[r][0])[k4] = make_float4(f0.x, f0.y, f1.x, f1.y);
    }
    __syncthreads();

    int cg = tid & 15;
    int rg = tid >> 4;
    int r0 = rg * 4;

    unsigned long long acc[4][4];
    #pragma unroll
    for (int a = 0; a < 4; a++)
        #pragma unroll
        for (int b = 0; b < 4; b++)
            acc[a][b] = 0ULL;

    #pragma unroll 8
    for (int kp = 0; kp < 32; kp++) {
        unsigned long long xv[4], wv[4];
        #pragma unroll
        for (int a = 0; a < 4; a++)
            xv[a] = *reinterpret_cast<const unsigned long long*>(&Xs[r0 + a][kp * 2]);
        #pragma unroll
        for (int b = 0; b < 4; b++)
            wv[b] = *reinterpret_cast<const unsigned long long*>(&Wt[cg + 16 * b][kp * 2]);
        #pragma unroll
        for (int a = 0; a < 4; a++)
            #pragma unroll
            for (int b = 0; b < 4; b++)
                asm("fma.rn.f32x2 %0, %1, %2, %0;"
                    : "+l"(acc[a][b]) : "l"(xv[a]), "l"(wv[b]));
    }

    #pragma unroll
    for (int a = 0; a < 4; a++) {
        int gr = row0 + r0 + a;
        if (gr < n1) {
            float di = g_dinv[gr];
            #pragma unroll
            for (int b = 0; b < 4; b++) {
                float lo, hi;
                asm("mov.b64 {%0,%1}, %2;" : "=f"(lo), "=f"(hi) : "l"(acc[a][b]));
                out[(size_t)gr * 64 + cg + 16 * b] = __float2half_rn((lo + hi) * di);
            }
        }
    }
}

// ------------------- pull aggregation, ranged [n0,n1) ----------
__global__ __launch_bounds__(256)
void k_pull(const __half* __restrict__ h, const float* __restrict__ bias,
            __half* __restrict__ out16, float* __restrict__ out32, int n0, int n1,
            const float* __restrict__ gam, const float* __restrict__ bet,
            const float* __restrict__ mu,  const float* __restrict__ var,
            int use_bn)
{
    int idx = blockIdx.x * blockDim.x + threadIdx.x;
    if (idx >= (n1 - n0) * 16) return;
    int i = n0 + (idx >> 4), k = idx & 15;

    const uint2* h2 = reinterpret_cast<const uint2*>(h);

    float4 acc;
    {   // self term
        uint2 sv = __ldg(&h2[(size_t)i * 16 + k]);
        float2 f0 = __half22float2(*reinterpret_cast<__half2*>(&sv.x));
        float2 f1 = __half22float2(*reinterpret_cast<__half2*>(&sv.y));
        acc.x = f0.x; acc.y = f0.y; acc.z = f1.x; acc.w = f1.y;
    }

    int p   = g_off[i];
    int end = g_off[i + 1];

    while (p + 16 <= end) {
        const int4* c4 = reinterpret_cast<const int4*>(&g_csr[p]);
        int4 a0 = __ldg(c4 + 0);
        int4 a1 = __ldg(c4 + 1);
        int4 a2 = __ldg(c4 + 2);
        int4 a3 = __ldg(c4 + 3);
        int cj[16] = { a0.x, a0.y, a0.z, a0.w,
                       a1.x, a1.y, a1.z, a1.w,
                       a2.x, a2.y, a2.z, a2.w,
                       a3.x, a3.y, a3.z, a3.w };
        #pragma unroll
        for (int jp = 0; jp < 8; jp++) {
            uint2 v0 = __ldg(&h2[(size_t)cj[2 * jp]     * 16 + k]);
            uint2 v1 = __ldg(&h2[(size_t)cj[2 * jp + 1] * 16 + k]);
            __half2 s0 = __hadd2(*reinterpret_cast<__half2*>(&v0.x),
                                 *reinterpret_cast<__half2*>(&v1.x));
            __half2 s1 = __hadd2(*reinterpret_cast<__half2*>(&v0.y),
                                 *reinterpret_cast<__half2*>(&v1.y));
            float2 f0 = __half22float2(s0);
            float2 f1 = __half22float2(s1);
            acc.x += f0.x; acc.y += f0.y; acc.z += f1.x; acc.w += f1.y;
        }
        p += 16;
    }
    if (p < end) {   // exactly 8 left (padding guarantees)
        const int4* c4 = reinterpret_cast<const int4*>(&g_csr[p]);
        int4 a0 = __ldg(c4 + 0);
        int4 a1 = __ldg(c4 + 1);
        int cj[8] = { a0.x, a0.y, a0.z, a0.w, a1.x, a1.y, a1.z, a1.w };
        #pragma unroll
        for (int jp = 0; jp < 4; jp++) {
            uint2 v0 = __ldg(&h2[(size_t)cj[2 * jp]     * 16 + k]);
            uint2 v1 = __ldg(&h2[(size_t)cj[2 * jp + 1] * 16 + k]);
            __half2 s0 = __hadd2(*reinterpret_cast<__half2*>(&v0.x),
                                 *reinterpret_cast<__half2*>(&v1.x));
            __half2 s1 = __hadd2(*reinterpret_cast<__half2*>(&v0.y),
                                 *reinterpret_cast<__half2*>(&v1.y));
            float2 f0 = __half22float2(s0);
            float2 f1 = __half22float2(s1);
            acc.x += f0.x; acc.y += f0.y; acc.z += f1.x; acc.w += f1.y;
        }
    }

    float di = g_dinv[i];
    float4 bv = reinterpret_cast<const float4*>(bias)[k];
    acc.x = fmaf(acc.x, di, bv.x);
    acc.y = fmaf(acc.y, di, bv.y);
    acc.z = fmaf(acc.z, di, bv.z);
    acc.w = fmaf(acc.w, di, bv.w);

    if (use_bn) {
        int k4 = k << 2;
        #pragma unroll
        for (int j = 0; j < 4; j++) {
            float a = gam[k4 + j] * rsqrtf(var[k4 + j] + EPS);
            float c = bet[k4 + j] - mu[k4 + j] * a;
            float* f = (&acc.x) + j;
            *f = fmaxf(fmaf(*f, a, c), 0.0f);
        }
    }

    if (out16) {
        __half2 r0 = __floats2half2_rn(acc.x, acc.y);
        __half2 r1 = __floats2half2_rn(acc.z, acc.w);
        uint2 st;
        st.x = *reinterpret_cast<unsigned*>(&r0);
        st.y = *reinterpret_cast<unsigned*>(&r1);
        reinterpret_cast<uint2*>(out16)[(size_t)i * 16 + k] = st;
    }
    if (out32)
        reinterpret_cast<float4*>(out32)[(size_t)i * 16 + k] = acc;
}

// ------------------- launch (forked + pipelined graph) -------------------
extern "C" void kernel_launch(void* const* d_in, const int* in_sizes, int n_in,
                              void* d_out, int out_size)
{
    const float* x   = (const float*)d_in[0];
    const int*   ei  = (const int*)  d_in[1];
    const float* W1  = (const float*)d_in[2];
    const float* b1  = (const float*)d_in[3];
    const float* g1  = (const float*)d_in[4];
    const float* be1 = (const float*)d_in[5];
    const float* m1  = (const float*)d_in[6];
    const float* v1  = (const float*)d_in[7];
    const float* W2  = (const float*)d_in[8];
    const float* b2  = (const float*)d_in[9];
    const float* g2  = (const float*)d_in[10];
    const float* be2 = (const float*)d_in[11];
    const float* m2  = (const float*)d_in[12];
    const float* v2  = (const float*)d_in[13];
    const float* W3  = (const float*)d_in[14];
    const float* b3  = (const float*)d_in[15];

    int N = in_sizes[0] / 64;
    int E = in_sizes[1] / 2;

    const int* row = ei;
    const int* col = ei + E;

    float* out  = (float*)d_out;
    float* emb  = out;                      // global_embeddings [N,64]
    float* pred = out + (size_t)N * 64;     // hc_predictions    [N,64]

    __half *p_h = nullptr, *p_hb = nullptr;
    cudaGetSymbolAddress((void**)&p_h,  g_h);
    cudaGetSymbolAddress((void**)&p_hb, g_hb);

    static cudaStream_t sA = nullptr, sB = nullptr;
    static cudaEvent_t ev[10];
    if (sA == nullptr) {
        cudaStreamCreateWithFlags(&sA, cudaStreamNonBlocking);
        cudaStreamCreateWithFlags(&sB, cudaStreamNonBlocking);
        for (int j = 0; j < 10; j++)
            cudaEventCreateWithFlags(&ev[j], cudaEventDisableTiming);
    }

    const int T = 256;
    int N2 = ((N / 2) + GEMM_ROWS - 1) / GEMM_ROWS * GEMM_ROWS;   // split point, 64-aligned
    if (N2 > N) N2 = N;

    int gN    = (N + T - 1) / T;
    int gE4   = (E + 4 * T - 1) / (4 * T);
    int gE8   = (E + 8 * T - 1) / (8 * T);
    int gN16  = (N * 16 + T - 1) / T;
    int gP1   = (N2 * 16 + T - 1) / T;              // pull lower half
    int gP2   = ((N - N2) * 16 + T - 1) / T;        // pull upper half
    int gG    = (N + GEMM_ROWS - 1) / GEMM_ROWS;
    int gGa   = N2 / GEMM_ROWS;                     // gemm lower half
    int gGb   = (N - N2 + GEMM_ROWS - 1) / GEMM_ROWS;
    int nb    = (N + SCAN_BLK - 1) / SCAN_BLK;

    // fork: gemm1 (unscaled) starts immediately, overlapping count
    cudaEventRecord(ev[0], 0);
    cudaStreamWaitEvent(sB, ev[0], 0);
    k_gemm_f32<<<gG, T, 0, sB>>>(x, W1, p_h, N);

    // main chain: count(+rank) -> scan(+dinv) -> build
    k_count  <<<gE4, T>>>(row, E);
    k_scan_lb<<<nb, SCAN_BLK>>>(N);
    cudaEventRecord(ev[1], 0);
    k_build  <<<gE8, T>>>(row, col, E);

    // branch A (after scan): pad + zero for next launch
    cudaStreamWaitEvent(sA, ev[1], 0);
    k_pad_zero<<<gN, T, 0, sA>>>(N);
    cudaEventRecord(ev[2], sA);

    // branch B (after scan): apply dinv to gemm1 output
    cudaStreamWaitEvent(sB, ev[1], 0);
    k_scale<<<gN16, T, 0, sB>>>(p_h, N);
    cudaEventRecord(ev[3], sB);

    // join
    cudaStreamWaitEvent(0, ev[2], 0);
    cudaStreamWaitEvent(0, ev[3], 0);

    // ---- boundary 1: pull1 (split) -> gemm2 (split, pipelined on sB) ----
    k_pull<<<gP1, T>>>(p_h, b1, p_hb, nullptr, 0, N2, g1, be1, m1, v1, 1);
    cudaEventRecord(ev[4], 0);
    k_pull<<<gP2, T>>>(p_h, b1, p_hb, nullptr, N2, N, g1, be1, m1, v1, 1);
    cudaEventRecord(ev[5], 0);

    cudaStreamWaitEvent(sB, ev[4], 0);
    k_gemm_f16<<<gGa, T, 0, sB>>>(p_hb, W2, p_h, 0, N2);
    cudaStreamWaitEvent(sB, ev[5], 0);
    k_gemm_f16<<<gGb, T, 0, sB>>>(p_hb, W2, p_h, N2, N);
    cudaEventRecord(ev[6], sB);
    cudaStreamWaitEvent(0, ev[6], 0);

    // ---- boundary 2: pull2 (split, writes emb) -> gemm3 (split, pipelined) ----
    k_pull<<<gP1, T>>>(p_h, b2, p_hb, emb, 0, N2, g2, be2, m2, v2, 1);
    cudaEventRecord(ev[7], 0);
    k_pull<<<gP2, T>>>(p_h, b2, p_hb, emb, N2, N, g2, be2, m2, v2, 1);
    cudaEventRecord(ev[8], 0);

    cudaStreamWaitEvent(sB, ev[7], 0);
    k_gemm_f16<<<gGa, T, 0, sB>>>(p_hb, W3, p_h, 0, N2);
    cudaStreamWaitEvent(sB, ev[8], 0);
    k_gemm_f16<<<gGb, T, 0, sB>>>(p_hb, W3, p_h, N2, N);
    cudaEventRecord(ev[9], sB);
    cudaStreamWaitEvent(0, ev[9], 0);

    // ---- final pull3: pred ----
    k_pull<<<gN16, T>>>(p_h, b3, nullptr, pred, 0, N, nullptr, nullptr, nullptr, nullptr, 0);
}

// round 13
// speedup vs baseline: 1.0573x; 1.0573x over previous
#include <cuda_runtime.h>
#include <cuda_fp16.h>
#include <math.h>

#define NMAX 100000
#define EMAX 1600000
#define CSRMAX (EMAX + 8 * NMAX)     // padded CSR capacity (pad to multiple of 8)
#define EPS 1e-5f
#define SCAN_BLK 1024
#define MAX_BLKS 128                 // ceil(100000/1024)=98 <= 128

// ---- device scratch (no allocations allowed). All zero at module load. ----
__device__ int      g_deg [NMAX];        // re-zeroed by k_pad_zero each launch
__device__ int      g_off [NMAX + 1];
__device__ unsigned g_state[MAX_BLKS];   // re-zeroed by k_pad_zero each launch
__device__ float    g_dinv[NMAX];
__device__ int      g_rank[EMAX];        // within-row rank of each edge
__device__ int      g_csr [CSRMAX];      // real slots by k_build, padding by k_pad_zero
__device__ __half   g_h   [(size_t)(NMAX + 1) * 64];  // gemm outputs; row NMAX never written => 0
__device__ __half   g_hb  [(size_t)(NMAX + 1) * 64];  // pull outputs; row NMAX never written => 0

// ---------- count + rank: vectorized (4 consecutive edges / thread) ----------
__global__ void k_count(const int* __restrict__ row, int E) {
    int t  = blockIdx.x * blockDim.x + threadIdx.x;
    int nv = E >> 2;                          // full int4 groups
    if (t < nv) {
        int4 r4 = __ldg(reinterpret_cast<const int4*>(row) + t);
        int4 k4;
        k4.x = atomicAdd(&g_deg[r4.x], 1);
        k4.y = atomicAdd(&g_deg[r4.y], 1);
        k4.z = atomicAdd(&g_deg[r4.z], 1);
        k4.w = atomicAdd(&g_deg[r4.w], 1);
        reinterpret_cast<int4*>(g_rank)[t] = k4;
    } else if (t == nv) {
        for (int e = nv << 2; e < E; e++)     // scalar tail (E%4)
            g_rank[e] = atomicAdd(&g_deg[row[e]], 1);
    }
}

// ---------- decoupled-lookback scan (warp-parallel lookback) + dinv ----------
__global__ __launch_bounds__(SCAN_BLK)
void k_scan_lb(int N) {
    __shared__ int warp_sums[32];
    __shared__ int s_prefix;

    int bid  = blockIdx.x;
    int tid  = threadIdx.x;
    int lane = tid & 31;
    int wid  = tid >> 5;
    int i    = bid * SCAN_BLK + tid;

    int v = (i < N) ? g_deg[i] : 0;
    if (i < N) g_dinv[i] = rsqrtf((float)v + 1.0f);   // +1 = self loop
    int vp = (v + 7) & ~7;                            // pad degree to multiple of 8

    int x = vp;
    #pragma unroll
    for (int d = 1; d < 32; d <<= 1) {
        int t = __shfl_up_sync(0xFFFFFFFFu, x, d);
        if (lane >= d) x += t;
    }
    if (lane == 31) warp_sums[wid] = x;
    __syncthreads();
    if (wid == 0) {
        int y = warp_sums[lane];
        #pragma unroll
        for (int d = 1; d < 32; d <<= 1) {
            int t = __shfl_up_sync(0xFFFFFFFFu, y, d);
            if (lane >= d) y += t;
        }
        warp_sums[lane] = y;
    }
    __syncthreads();

    int block_incl  = x + (wid > 0 ? warp_sums[wid - 1] : 0);
    int block_total = warp_sums[31];

    if (wid == 0) {
        if (bid == 0) {
            if (lane == 0) {
                s_prefix = 0;
                atomicExch(&g_state[0], (2u << 28) | (unsigned)block_total);
            }
        } else {
            if (lane == 0)
                atomicExch(&g_state[bid], (1u << 28) | (unsigned)block_total);
            int run = 0;
            int j0 = bid - 1;
            while (true) {
                int idx = j0 - lane;
                unsigned st = (idx >= 0) ? atomicAdd(&g_state[idx], 0u) : (2u << 28);
                if (__any_sync(0xFFFFFFFFu, (st >> 28) == 0u)) { __nanosleep(20); continue; }
                unsigned pm = __ballot_sync(0xFFFFFFFFu, (st >> 28) == 2u);
                if (pm) {
                    int L = __ffs((int)pm) - 1;
                    int val = (lane <= L) ? (int)(st & 0x0FFFFFFFu) : 0;
                    run += __reduce_add_sync(0xFFFFFFFFu, val);
                    break;
                } else {
                    run += __reduce_add_sync(0xFFFFFFFFu, (int)(st & 0x0FFFFFFFu));
                    j0 -= 32;
                }
            }
            if (lane == 0) {
                s_prefix = run;
                atomicExch(&g_state[bid], (2u << 28) | (unsigned)(run + block_total));
            }
        }
    }
    __syncthreads();

    if (tid == 0 && bid == (int)gridDim.x - 1)
        g_off[N] = s_prefix + block_total;

    int ex = s_prefix + block_incl - vp;              // exclusive prefix (8-aligned)
    if (i < N) g_off[i] = ex;
}

// ---------- pad padding slots + zero deg/state for the NEXT launch ----------
__global__ void k_pad_zero(int N) {
    int i = blockIdx.x * blockDim.x + threadIdx.x;
    if (i < MAX_BLKS) g_state[i] = 0;
    if (i >= N) return;
    int d = g_deg[i];
    int p = g_off[i] + d;
    int e = g_off[i] + ((d + 7) & ~7);
    for (; p < e; p++) g_csr[p] = NMAX;
    g_deg[i] = 0;
}

// ---------- scatter real edges: NO atomics, vectorized streams ----------
__global__ void k_build(const int* __restrict__ row, const int* __restrict__ col, int E) {
    int t  = blockIdx.x * blockDim.x + threadIdx.x;
    int nv = E >> 2;
    if (t < nv) {
        int4 r4 = __ldg(reinterpret_cast<const int4*>(row) + t);
        int4 c4 = __ldg(reinterpret_cast<const int4*>(col) + t);
        int4 k4 = reinterpret_cast<const int4*>(g_rank)[t];
        int p0 = __ldg(&g_off[r4.x]);
        int p1 = __ldg(&g_off[r4.y]);
        int p2 = __ldg(&g_off[r4.z]);
        int p3 = __ldg(&g_off[r4.w]);
        g_csr[p0 + k4.x] = c4.x;
        g_csr[p1 + k4.y] = c4.y;
        g_csr[p2 + k4.z] = c4.z;
        g_csr[p3 + k4.w] = c4.w;
    } else if (t == nv) {
        for (int e = nv << 2; e < E; e++)
            g_csr[g_off[row[e]] + g_rank[e]] = col[e];
    }
}

// ---------- scale: h[i,:] *= dinv[i] (fp32 math, fp16 storage) ----------
__global__ void k_scale(__half* __restrict__ h, int N) {
    int idx = blockIdx.x * blockDim.x + threadIdx.x;
    if (idx >= N * 16) return;
    int i = idx >> 4;
    float di = g_dinv[i];
    uint2* h2 = reinterpret_cast<uint2*>(h);
    uint2 v = h2[idx];
    float2 f0 = __half22float2(*reinterpret_cast<__half2*>(&v.x));
    float2 f1 = __half22float2(*reinterpret_cast<__half2*>(&v.y));
    __half2 r0 = __floats2half2_rn(f0.x * di, f0.y * di);
    __half2 r1 = __floats2half2_rn(f1.x * di, f1.y * di);
    uint2 st;
    st.x = *reinterpret_cast<unsigned*>(&r0);
    st.y = *reinterpret_cast<unsigned*>(&r1);
    h2[idx] = st;
}

// ------------------- GEMM (fp32 input, NO dinv scale): layer-1 early start ----------
#define GEMM_ROWS 64

__global__ __launch_bounds__(256)
void k_gemm_f32(const float* __restrict__ in, const float* __restrict__ W,
                __half* __restrict__ out, int N)
{
    __shared__ float Wt[64][66];
    __shared__ float Xs[GEMM_ROWS][64];

    int tid = threadIdx.x;
    int row0 = blockIdx.x * GEMM_ROWS;

    #pragma unroll
    for (int i = tid; i < 64 * 64; i += 256) {
        int k = i >> 6, c = i & 63;
        Wt[c][k] = W[i];
    }
    #pragma unroll
    for (int i = tid; i < GEMM_ROWS * 16; i += 256) {
        int r = i >> 4, k4 = (i & 15);
        int gr = row0 + r;
        float4 v = (gr < N) ? reinterpret_cast<const float4*>(in)[(size_t)gr * 16 + k4]
                            : make_float4(0.f, 0.f, 0.f, 0.f);
        reinterpret_cast<float4*>(&Xs[r][0])[k4] = v;
    }
    __syncthreads();

    int cg = tid & 15;
    int rg = tid >> 4;
    int r0 = rg * 4;

    unsigned long long acc[4][4];
    #pragma unroll
    for (int a = 0; a < 4; a++)
        #pragma unroll
        for (int b = 0; b < 4; b++)
            acc[a][b] = 0ULL;

    #pragma unroll 8
    for (int kp = 0; kp < 32; kp++) {
        unsigned long long xv[4], wv[4];
        #pragma unroll
        for (int a = 0; a < 4; a++)
            xv[a] = *reinterpret_cast<const unsigned long long*>(&Xs[r0 + a][kp * 2]);
        #pragma unroll
        for (int b = 0; b < 4; b++)
            wv[b] = *reinterpret_cast<const unsigned long long*>(&Wt[cg + 16 * b][kp * 2]);
        #pragma unroll
        for (int a = 0; a < 4; a++)
            #pragma unroll
            for (int b = 0; b < 4; b++)
                asm("fma.rn.f32x2 %0, %1, %2, %0;"
                    : "+l"(acc[a][b]) : "l"(xv[a]), "l"(wv[b]));
    }

    #pragma unroll
    for (int a = 0; a < 4; a++) {
        int gr = row0 + r0 + a;
        if (gr < N) {
            #pragma unroll
            for (int b = 0; b < 4; b++) {
                float lo, hi;
                asm("mov.b64 {%0,%1}, %2;" : "=f"(lo), "=f"(hi) : "l"(acc[a][b]));
                out[(size_t)gr * 64 + cg + 16 * b] = __float2half_rn(lo + hi);
            }
        }
    }
}

// ------------------- GEMM (fp16 input, dinv-scaled fp16 out) ----------
__global__ __launch_bounds__(256)
void k_gemm_f16(const __half* __restrict__ in, const float* __restrict__ W,
                __half* __restrict__ out, int N)
{
    __shared__ float Wt[64][66];
    __shared__ float Xs[GEMM_ROWS][64];

    int tid = threadIdx.x;
    int row0 = blockIdx.x * GEMM_ROWS;

    #pragma unroll
    for (int i = tid; i < 64 * 64; i += 256) {
        int k = i >> 6, c = i & 63;
        Wt[c][k] = W[i];
    }
    #pragma unroll
    for (int i = tid; i < GEMM_ROWS * 16; i += 256) {
        int r = i >> 4, k4 = (i & 15);
        int gr = row0 + r;
        uint2 v = (gr < N) ? reinterpret_cast<const uint2*>(in)[(size_t)gr * 16 + k4]
                           : make_uint2(0u, 0u);
        float2 f0 = __half22float2(*reinterpret_cast<__half2*>(&v.x));
        float2 f1 = __half22float2(*reinterpret_cast<__half2*>(&v.y));
        reinterpret_cast<float4*>(&Xs[r][0])[k4] = make_float4(f0.x, f0.y, f1.x, f1.y);
    }
    __syncthreads();

    int cg = tid & 15;
    int rg = tid >> 4;
    int r0 = rg * 4;

    unsigned long long acc[4][4];
    #pragma unroll
    for (int a = 0; a < 4; a++)
        #pragma unroll
        for (int b = 0; b < 4; b++)
            acc[a][b] = 0ULL;

    #pragma unroll 8
    for (int kp = 0; kp < 32; kp++) {
        unsigned long long xv[4], wv[4];
        #pragma unroll
        for (int a = 0; a < 4; a++)
            xv[a] = *reinterpret_cast<const unsigned long long*>(&Xs[r0 + a][kp * 2]);
        #pragma unroll
        for (int b = 0; b < 4; b++)
            wv[b] = *reinterpret_cast<const unsigned long long*>(&Wt[cg + 16 * b][kp * 2]);
        #pragma unroll
        for (int a = 0; a < 4; a++)
            #pragma unroll
            for (int b = 0; b < 4; b++)
                asm("fma.rn.f32x2 %0, %1, %2, %0;"
                    : "+l"(acc[a][b]) : "l"(xv[a]), "l"(wv[b]));
    }

    #pragma unroll
    for (int a = 0; a < 4; a++) {
        int gr = row0 + r0 + a;
        if (gr < N) {
            float di = g_dinv[gr];
            #pragma unroll
            for (int b = 0; b < 4; b++) {
                float lo, hi;
                asm("mov.b64 {%0,%1}, %2;" : "=f"(lo), "=f"(hi) : "l"(acc[a][b]));
                out[(size_t)gr * 64 + cg + 16 * b] = __float2half_rn((lo + hi) * di);
            }
        }
    }
}

// ------------------- pull aggregation (fp16 gathers, fp32 accumulate) ----------
// 16-chunk fast path + exact 8-tail (offsets padded to multiple of 8).
__global__ __launch_bounds__(256)
void k_pull(const __half* __restrict__ h, const float* __restrict__ bias,
            __half* __restrict__ out16, float* __restrict__ out32, int N,
            const float* __restrict__ gam, const float* __restrict__ bet,
            const float* __restrict__ mu,  const float* __restrict__ var,
            int use_bn)
{
    int idx = blockIdx.x * blockDim.x + threadIdx.x;
    if (idx >= N * 16) return;
    int i = idx >> 4, k = idx & 15;

    const uint2* h2 = reinterpret_cast<const uint2*>(h);

    float4 acc;
    {   // self term
        uint2 sv = __ldg(&h2[(size_t)i * 16 + k]);
        float2 f0 = __half22float2(*reinterpret_cast<__half2*>(&sv.x));
        float2 f1 = __half22float2(*reinterpret_cast<__half2*>(&sv.y));
        acc.x = f0.x; acc.y = f0.y; acc.z = f1.x; acc.w = f1.y;
    }

    int p   = g_off[i];
    int end = g_off[i + 1];

    while (p + 16 <= end) {
        const int4* c4 = reinterpret_cast<const int4*>(&g_csr[p]);
        int4 a0 = __ldg(c4 + 0);
        int4 a1 = __ldg(c4 + 1);
        int4 a2 = __ldg(c4 + 2);
        int4 a3 = __ldg(c4 + 3);
        int cj[16] = { a0.x, a0.y, a0.z, a0.w,
                       a1.x, a1.y, a1.z, a1.w,
                       a2.x, a2.y, a2.z, a2.w,
                       a3.x, a3.y, a3.z, a3.w };
        #pragma unroll
        for (int jp = 0; jp < 8; jp++) {
            uint2 v0 = __ldg(&h2[(size_t)cj[2 * jp]     * 16 + k]);
            uint2 v1 = __ldg(&h2[(size_t)cj[2 * jp + 1] * 16 + k]);
            __half2 s0 = __hadd2(*reinterpret_cast<__half2*>(&v0.x),
                                 *reinterpret_cast<__half2*>(&v1.x));
            __half2 s1 = __hadd2(*reinterpret_cast<__half2*>(&v0.y),
                                 *reinterpret_cast<__half2*>(&v1.y));
            float2 f0 = __half22float2(s0);
            float2 f1 = __half22float2(s1);
            acc.x += f0.x; acc.y += f0.y; acc.z += f1.x; acc.w += f1.y;
        }
        p += 16;
    }
    if (p < end) {   // exactly 8 left (padding guarantees)
        const int4* c4 = reinterpret_cast<const int4*>(&g_csr[p]);
        int4 a0 = __ldg(c4 + 0);
        int4 a1 = __ldg(c4 + 1);
        int cj[8] = { a0.x, a0.y, a0.z, a0.w, a1.x, a1.y, a1.z, a1.w };
        #pragma unroll
        for (int jp = 0; jp < 4; jp++) {
            uint2 v0 = __ldg(&h2[(size_t)cj[2 * jp]     * 16 + k]);
            uint2 v1 = __ldg(&h2[(size_t)cj[2 * jp + 1] * 16 + k]);
            __half2 s0 = __hadd2(*reinterpret_cast<__half2*>(&v0.x),
                                 *reinterpret_cast<__half2*>(&v1.x));
            __half2 s1 = __hadd2(*reinterpret_cast<__half2*>(&v0.y),
                                 *reinterpret_cast<__half2*>(&v1.y));
            float2 f0 = __half22float2(s0);
            float2 f1 = __half22float2(s1);
            acc.x += f0.x; acc.y += f0.y; acc.z += f1.x; acc.w += f1.y;
        }
    }

    float di = g_dinv[i];
    float4 bv = reinterpret_cast<const float4*>(bias)[k];
    acc.x = fmaf(acc.x, di, bv.x);
    acc.y = fmaf(acc.y, di, bv.y);
    acc.z = fmaf(acc.z, di, bv.z);
    acc.w = fmaf(acc.w, di, bv.w);

    if (use_bn) {
        int k4 = k << 2;
        #pragma unroll
        for (int j = 0; j < 4; j++) {
            float a = gam[k4 + j] * rsqrtf(var[k4 + j] + EPS);
            float c = bet[k4 + j] - mu[k4 + j] * a;
            float* f = (&acc.x) + j;
            *f = fmaxf(fmaf(*f, a, c), 0.0f);
        }
    }

    if (out16) {
        __half2 r0 = __floats2half2_rn(acc.x, acc.y);
        __half2 r1 = __floats2half2_rn(acc.z, acc.w);
        uint2 st;
        st.x = *reinterpret_cast<unsigned*>(&r0);
        st.y = *reinterpret_cast<unsigned*>(&r1);
        reinterpret_cast<uint2*>(out16)[(size_t)i * 16 + k] = st;
    }
    if (out32)
        reinterpret_cast<float4*>(out32)[(size_t)i * 16 + k] = acc;
}

// ------------------- launch (forked-graph orchestration, R11 structure) -------------------
extern "C" void kernel_launch(void* const* d_in, const int* in_sizes, int n_in,
                              void* d_out, int out_size)
{
    const float* x   = (const float*)d_in[0];
    const int*   ei  = (const int*)  d_in[1];
    const float* W1  = (const float*)d_in[2];
    const float* b1  = (const float*)d_in[3];
    const float* g1  = (const float*)d_in[4];
    const float* be1 = (const float*)d_in[5];
    const float* m1  = (const float*)d_in[6];
    const float* v1  = (const float*)d_in[7];
    const float* W2  = (const float*)d_in[8];
    const float* b2  = (const float*)d_in[9];
    const float* g2  = (const float*)d_in[10];
    const float* be2 = (const float*)d_in[11];
    const float* m2  = (const float*)d_in[12];
    const float* v2  = (const float*)d_in[13];
    const float* W3  = (const float*)d_in[14];
    const float* b3  = (const float*)d_in[15];

    int N = in_sizes[0] / 64;
    int E = in_sizes[1] / 2;

    const int* row = ei;
    const int* col = ei + E;

    float* out  = (float*)d_out;
    float* emb  = out;                      // global_embeddings [N,64]
    float* pred = out + (size_t)N * 64;     // hc_predictions    [N,64]

    __half *p_h = nullptr, *p_hb = nullptr;
    cudaGetSymbolAddress((void**)&p_h,  g_h);
    cudaGetSymbolAddress((void**)&p_hb, g_hb);

    static cudaStream_t sA = nullptr, sB = nullptr;
    static cudaEvent_t evFork = nullptr, evScan = nullptr, evA = nullptr, evB = nullptr;
    if (sA == nullptr) {
        cudaStreamCreateWithFlags(&sA, cudaStreamNonBlocking);
        cudaStreamCreateWithFlags(&sB, cudaStreamNonBlocking);
        cudaEventCreateWithFlags(&evFork, cudaEventDisableTiming);
        cudaEventCreateWithFlags(&evScan, cudaEventDisableTiming);
        cudaEventCreateWithFlags(&evA,    cudaEventDisableTiming);
        cudaEventCreateWithFlags(&evB,    cudaEventDisableTiming);
    }

    const int T = 256;
    int gN   = (N + T - 1) / T;
    int gV   = ((E >> 2) + 1 + T - 1) / T;   // vectorized edge kernels (+1 tail thread)
    int gN16 = (N * 16 + T - 1) / T;
    int gG   = (N + GEMM_ROWS - 1) / GEMM_ROWS;
    int nb   = (N + SCAN_BLK - 1) / SCAN_BLK;

    // fork: gemm1 (unscaled) starts immediately, overlapping count
    cudaEventRecord(evFork, 0);
    cudaStreamWaitEvent(sB, evFork, 0);
    k_gemm_f32<<<gG, T, 0, sB>>>(x, W1, p_h, N);

    // main chain: count(+rank) -> scan(+dinv) -> build (no atomics)
    k_count  <<<gV, T>>>(row, E);
    k_scan_lb<<<nb, SCAN_BLK>>>(N);
    cudaEventRecord(evScan, 0);
    k_build  <<<gV, T>>>(row, col, E);

    // branch A (after scan): pad padding slots + zero deg/state for next launch
    cudaStreamWaitEvent(sA, evScan, 0);
    k_pad_zero<<<gN, T, 0, sA>>>(N);
    cudaEventRecord(evA, sA);

    // branch B (after scan): apply dinv to gemm1 output
    cudaStreamWaitEvent(sB, evScan, 0);
    k_scale<<<gN16, T, 0, sB>>>(p_h, N);
    cudaEventRecord(evB, sB);

    // join
    cudaStreamWaitEvent(0, evA, 0);
    cudaStreamWaitEvent(0, evB, 0);

    // ---- layer 1: hb = fp16( relu(bn1(agg(h) + b1)) ) ----
    k_pull<<<gN16, T>>>(p_h, b1, p_hb, nullptr, N, g1, be1, m1, v1, 1);

    // ---- layer 2: h = gemm(hb, W2)*dinv; emb/hb = relu(bn2(agg(h) + b2)) ----
    k_gemm_f16<<<gG, T>>>(p_hb, W2, p_h, N);
    k_pull<<<gN16, T>>>(p_h, b2, p_hb, emb, N, g2, be2, m2, v2, 1);

    // ---- layer 3: h = gemm(hb, W3)*dinv; pred = agg(h) + b3 ----
    k_gemm_f16<<<gG, T>>>(p_hb, W3, p_h, N);
    k_pull<<<gN16, T>>>(p_h, b3, nullptr, pred, N, nullptr, nullptr, nullptr, nullptr, 0);
}

// round 15
// speedup vs baseline: 1.1794x; 1.1155x over previous
#include <cuda_runtime.h>
#include <cuda_fp16.h>
#include <math.h>

#define NMAX 100000
#define EMAX 1600000
#define CSRMAX (EMAX + 8 * NMAX)     // padded CSR capacity (pad to multiple of 8)
#define EPS 1e-5f
#define SCAN_BLK 1024
#define MAX_BLKS 128                 // ceil(100000/1024)=98 <= 128

// ---- device scratch (no allocations allowed). All zero at module load. ----
__device__ int      g_deg [NMAX];        // re-zeroed by k_pad_zero each launch
__device__ int      g_off [NMAX + 1];
__device__ unsigned g_state[MAX_BLKS];   // re-zeroed by k_pad_zero each launch
__device__ float    g_dinv[NMAX];
__device__ int      g_rank[EMAX];        // within-row rank of each edge
__device__ int      g_csr [CSRMAX];      // real slots by k_build, padding by k_pad_zero
__device__ __half   g_h   [(size_t)(NMAX + 1) * 64];  // gemm outputs; row NMAX never written => 0
__device__ __half   g_hb  [(size_t)(NMAX + 1) * 64];  // pull outputs; row NMAX never written => 0

// ---------- count + rank: vectorized (4 consecutive edges / thread) ----------
__global__ void k_count(const int* __restrict__ row, int E) {
    int t  = blockIdx.x * blockDim.x + threadIdx.x;
    int nv = E >> 2;                          // full int4 groups
    if (t < nv) {
        int4 r4 = __ldg(reinterpret_cast<const int4*>(row) + t);
        int4 k4;
        k4.x = atomicAdd(&g_deg[r4.x], 1);
        k4.y = atomicAdd(&g_deg[r4.y], 1);
        k4.z = atomicAdd(&g_deg[r4.z], 1);
        k4.w = atomicAdd(&g_deg[r4.w], 1);
        reinterpret_cast<int4*>(g_rank)[t] = k4;
    } else if (t == nv) {
        for (int e = nv << 2; e < E; e++)     // scalar tail (E%4)
            g_rank[e] = atomicAdd(&g_deg[row[e]], 1);
    }
}

// ---------- decoupled-lookback scan (warp-parallel lookback) + dinv ----------
__global__ __launch_bounds__(SCAN_BLK)
void k_scan_lb(int N) {
    __shared__ int warp_sums[32];
    __shared__ int s_prefix;

    int bid  = blockIdx.x;
    int tid  = threadIdx.x;
    int lane = tid & 31;
    int wid  = tid >> 5;
    int i    = bid * SCAN_BLK + tid;

    int v = (i < N) ? g_deg[i] : 0;
    if (i < N) g_dinv[i] = rsqrtf((float)v + 1.0f);   // +1 = self loop
    int vp = (v + 7) & ~7;                            // pad degree to multiple of 8

    int x = vp;
    #pragma unroll
    for (int d = 1; d < 32; d <<= 1) {
        int t = __shfl_up_sync(0xFFFFFFFFu, x, d);
        if (lane >= d) x += t;
    }
    if (lane == 31) warp_sums[wid] = x;
    __syncthreads();
    if (wid == 0) {
        int y = warp_sums[lane];
        #pragma unroll
        for (int d = 1; d < 32; d <<= 1) {
            int t = __shfl_up_sync(0xFFFFFFFFu, y, d);
            if (lane >= d) y += t;
        }
        warp_sums[lane] = y;
    }
    __syncthreads();

    int block_incl  = x + (wid > 0 ? warp_sums[wid - 1] : 0);
    int block_total = warp_sums[31];

    if (wid == 0) {
        if (bid == 0) {
            if (lane == 0) {
                s_prefix = 0;
                atomicExch(&g_state[0], (2u << 28) | (unsigned)block_total);
            }
        } else {
            if (lane == 0)
                atomicExch(&g_state[bid], (1u << 28) | (unsigned)block_total);
            int run = 0;
            int j0 = bid - 1;
            while (true) {
                int idx = j0 - lane;
                unsigned st = (idx >= 0) ? atomicAdd(&g_state[idx], 0u) : (2u << 28);
                if (__any_sync(0xFFFFFFFFu, (st >> 28) == 0u)) { __nanosleep(20); continue; }
                unsigned pm = __ballot_sync(0xFFFFFFFFu, (st >> 28) == 2u);
                if (pm) {
                    int L = __ffs((int)pm) - 1;
                    int val = (lane <= L) ? (int)(st & 0x0FFFFFFFu) : 0;
                    run += __reduce_add_sync(0xFFFFFFFFu, val);
                    break;
                } else {
                    run += __reduce_add_sync(0xFFFFFFFFu, (int)(st & 0x0FFFFFFFu));
                    j0 -= 32;
                }
            }
            if (lane == 0) {
                s_prefix = run;
                atomicExch(&g_state[bid], (2u << 28) | (unsigned)(run + block_total));
            }
        }
    }
    __syncthreads();

    if (tid == 0 && bid == (int)gridDim.x - 1)
        g_off[N] = s_prefix + block_total;

    int ex = s_prefix + block_incl - vp;              // exclusive prefix (8-aligned)
    if (i < N) g_off[i] = ex;
}

// ---------- pad padding slots + zero deg/state for the NEXT launch ----------
__global__ void k_pad_zero(int N) {
    int i = blockIdx.x * blockDim.x + threadIdx.x;
    if (i < MAX_BLKS) g_state[i] = 0;
    if (i >= N) return;
    int d = g_deg[i];
    int p = g_off[i] + d;
    int e = g_off[i] + ((d + 7) & ~7);
    for (; p < e; p++) g_csr[p] = NMAX;
    g_deg[i] = 0;
}

// ---------- scatter real edges: NO atomics, vectorized streams ----------
__global__ void k_build(const int* __restrict__ row, const int* __restrict__ col, int E) {
    int t  = blockIdx.x * blockDim.x + threadIdx.x;
    int nv = E >> 2;
    if (t < nv) {
        int4 r4 = __ldg(reinterpret_cast<const int4*>(row) + t);
        int4 c4 = __ldg(reinterpret_cast<const int4*>(col) + t);
        int4 k4 = reinterpret_cast<const int4*>(g_rank)[t];
        int p0 = __ldg(&g_off[r4.x]);
        int p1 = __ldg(&g_off[r4.y]);
        int p2 = __ldg(&g_off[r4.z]);
        int p3 = __ldg(&g_off[r4.w]);
        g_csr[p0 + k4.x] = c4.x;
        g_csr[p1 + k4.y] = c4.y;
        g_csr[p2 + k4.z] = c4.z;
        g_csr[p3 + k4.w] = c4.w;
    } else if (t == nv) {
        for (int e = nv << 2; e < E; e++)
            g_csr[g_off[row[e]] + g_rank[e]] = col[e];
    }
}

// ---------- scale: h[i,:] *= dinv[i] (fp32 math, fp16 storage) ----------
__global__ void k_scale(__half* __restrict__ h, int N) {
    int idx = blockIdx.x * blockDim.x + threadIdx.x;
    if (idx >= N * 16) return;
    int i = idx >> 4;
    float di = g_dinv[i];
    uint2* h2 = reinterpret_cast<uint2*>(h);
    uint2 v = h2[idx];
    float2 f0 = __half22float2(*reinterpret_cast<__half2*>(&v.x));
    float2 f1 = __half22float2(*reinterpret_cast<__half2*>(&v.y));
    __half2 r0 = __floats2half2_rn(f0.x * di, f0.y * di);
    __half2 r1 = __floats2half2_rn(f1.x * di, f1.y * di);
    uint2 st;
    st.x = *reinterpret_cast<unsigned*>(&r0);
    st.y = *reinterpret_cast<unsigned*>(&r1);
    h2[idx] = st;
}

// ------------------- GEMM (fp32 input, NO dinv scale): layer-1 early start ----------
#define GEMM_ROWS 64

__global__ __launch_bounds__(256)
void k_gemm_f32(const float* __restrict__ in, const float* __restrict__ W,
                __half* __restrict__ out, int N)
{
    __shared__ float Wt[64][66];
    __shared__ float Xs[GEMM_ROWS][64];

    int tid = threadIdx.x;
    int row0 = blockIdx.x * GEMM_ROWS;

    #pragma unroll
    for (int i = tid; i < 64 * 64; i += 256) {
        int k = i >> 6, c = i & 63;
        Wt[c][k] = W[i];
    }
    #pragma unroll
    for (int i = tid; i < GEMM_ROWS * 16; i += 256) {
        int r = i >> 4, k4 = (i & 15);
        int gr = row0 + r;
        float4 v = (gr < N) ? reinterpret_cast<const float4*>(in)[(size_t)gr * 16 + k4]
                            : make_float4(0.f, 0.f, 0.f, 0.f);
        reinterpret_cast<float4*>(&Xs[r][0])[k4] = v;
    }
    __syncthreads();

    int cg = tid & 15;
    int rg = tid >> 4;
    int r0 = rg * 4;

    unsigned long long acc[4][4];
    #pragma unroll
    for (int a = 0; a < 4; a++)
        #pragma unroll
        for (int b = 0; b < 4; b++)
            acc[a][b] = 0ULL;

    #pragma unroll 8
    for (int kp = 0; kp < 32; kp++) {
        unsigned long long xv[4], wv[4];
        #pragma unroll
        for (int a = 0; a < 4; a++)
            xv[a] = *reinterpret_cast<const unsigned long long*>(&Xs[r0 + a][kp * 2]);
        #pragma unroll
        for (int b = 0; b < 4; b++)
            wv[b] = *reinterpret_cast<const unsigned long long*>(&Wt[cg + 16 * b][kp * 2]);
        #pragma unroll
        for (int a = 0; a < 4; a++)
            #pragma unroll
            for (int b = 0; b < 4; b++)
                asm("fma.rn.f32x2 %0, %1, %2, %0;"
                    : "+l"(acc[a][b]) : "l"(xv[a]), "l"(wv[b]));
    }

    #pragma unroll
    for (int a = 0; a < 4; a++) {
        int gr = row0 + r0 + a;
        if (gr < N) {
            #pragma unroll
            for (int b = 0; b < 4; b++) {
                float lo, hi;
                asm("mov.b64 {%0,%1}, %2;" : "=f"(lo), "=f"(hi) : "l"(acc[a][b]));
                out[(size_t)gr * 64 + cg + 16 * b] = __float2half_rn(lo + hi);
            }
        }
    }
}

// ------------------- HMMA GEMM (fp16 input, dinv-scaled fp16 out): layers 2-3 ----------
// 128 threads = 4 warps, 64 rows/CTA. Each warp: 16 rows x 64 cols via
// mma.sync.m16n8k16 (4 K-steps x 8 N-tiles). Smem rows padded to 72 halves
// -> the (g,t) fragment access pattern is bank-conflict-free.
__global__ __launch_bounds__(128)
void k_gemm_mma(const __half* __restrict__ in, const float* __restrict__ W,
                __half* __restrict__ out, int N)
{
    __shared__ __half Xs[64][72];
    __shared__ __half Wt[64][72];    // Wt[n][k] = f16(W[k][n])

    int tid = threadIdx.x;
    int row0 = blockIdx.x * 64;

    // A tile: 64 rows x 64 f16, uint4 (16B) chunks into padded rows
    for (int j = tid; j < 512; j += 128) {
        int r = j >> 3, c = j & 7;
        int gr = row0 + r;
        uint4 v = make_uint4(0u, 0u, 0u, 0u);
        if (gr < N)
            v = __ldg(reinterpret_cast<const uint4*>(in + (size_t)gr * 64) + c);
        *reinterpret_cast<uint4*>(&Xs[r][c * 8]) = v;
    }
    // W transpose + fp16 convert: float4 over n
    for (int j = tid; j < 1024; j += 128) {
        int k = j >> 4, n4 = (j & 15) * 4;
        float4 w = __ldg(reinterpret_cast<const float4*>(W + k * 64 + n4));
        Wt[n4 + 0][k] = __float2half_rn(w.x);
        Wt[n4 + 1][k] = __float2half_rn(w.y);
        Wt[n4 + 2][k] = __float2half_rn(w.z);
        Wt[n4 + 3][k] = __float2half_rn(w.w);
    }
    __syncthreads();

    int w    = tid >> 5;
    int lane = tid & 31;
    int g    = lane >> 2;      // 0..7
    int t    = lane & 3;       // 0..3
    int ra   = w * 16 + g;     // A row for a0/a2 (a1/a3: +8)

    float c[8][4];
    #pragma unroll
    for (int nt = 0; nt < 8; nt++)
        #pragma unroll
        for (int q = 0; q < 4; q++)
            c[nt][q] = 0.0f;

    #pragma unroll
    for (int ks = 0; ks < 4; ks++) {
        int k0 = ks * 16;
        unsigned a0 = *reinterpret_cast<const unsigned*>(&Xs[ra    ][k0 + 2 * t    ]);
        unsigned a1 = *reinterpret_cast<const unsigned*>(&Xs[ra + 8][k0 + 2 * t    ]);
        unsigned a2 = *reinterpret_cast<const unsigned*>(&Xs[ra    ][k0 + 2 * t + 8]);
        unsigned a3 = *reinterpret_cast<const unsigned*>(&Xs[ra + 8][k0 + 2 * t + 8]);
        #pragma unroll
        for (int nt = 0; nt < 8; nt++) {
            unsigned b0 = *reinterpret_cast<const unsigned*>(&Wt[nt * 8 + g][k0 + 2 * t    ]);
            unsigned b1 = *reinterpret_cast<const unsigned*>(&Wt[nt * 8 + g][k0 + 2 * t + 8]);
            asm volatile(
                "mma.sync.aligned.m16n8k16.row.col.f32.f16.f16.f32 "
                "{%0,%1,%2,%3}, {%4,%5,%6,%7}, {%8,%9}, {%0,%1,%2,%3};"
                : "+f"(c[nt][0]), "+f"(c[nt][1]), "+f"(c[nt][2]), "+f"(c[nt][3])
                : "r"(a0), "r"(a1), "r"(a2), "r"(a3), "r"(b0), "r"(b1));
        }
    }

    // epilogue: rows m0 = row0 + w*16 + g, m1 = m0 + 8; cols nt*8 + 2t, +1
    int m0 = row0 + w * 16 + g;
    int m1 = m0 + 8;
    float d0 = (m0 < N) ? g_dinv[m0] : 0.0f;
    float d1 = (m1 < N) ? g_dinv[m1] : 0.0f;
    #pragma unroll
    for (int nt = 0; nt < 8; nt++) {
        int col = nt * 8 + 2 * t;
        if (m0 < N) {
            __half2 p = __floats2half2_rn(c[nt][0] * d0, c[nt][1] * d0);
            *reinterpret_cast<unsigned*>(out + (size_t)m0 * 64 + col) =
                *reinterpret_cast<unsigned*>(&p);
        }
        if (m1 < N) {
            __half2 p = __floats2half2_rn(c[nt][2] * d1, c[nt][3] * d1);
            *reinterpret_cast<unsigned*>(out + (size_t)m1 * 64 + col) =
                *reinterpret_cast<unsigned*>(&p);
        }
    }
}

// ------------------- pull aggregation (fp16 gathers, fp32 accumulate) ----------
// 16-chunk fast path + exact 8-tail (offsets padded to multiple of 8).
__global__ __launch_bounds__(256)
void k_pull(const __half* __restrict__ h, const float* __restrict__ bias,
            __half* __restrict__ out16, float* __restrict__ out32, int N,
            const float* __restrict__ gam, const float* __restrict__ bet,
            const float* __restrict__ mu,  const float* __restrict__ var,
            int use_bn)
{
    int idx = blockIdx.x * blockDim.x + threadIdx.x;
    if (idx >= N * 16) return;
    int i = idx >> 4, k = idx & 15;

    const uint2* h2 = reinterpret_cast<const uint2*>(h);

    float4 acc;
    {   // self term
        uint2 sv = __ldg(&h2[(size_t)i * 16 + k]);
        float2 f0 = __half22float2(*reinterpret_cast<__half2*>(&sv.x));
        float2 f1 = __half22float2(*reinterpret_cast<__half2*>(&sv.y));
        acc.x = f0.x; acc.y = f0.y; acc.z = f1.x; acc.w = f1.y;
    }

    int p   = g_off[i];
    int end = g_off[i + 1];

    while (p + 16 <= end) {
        const int4* c4 = reinterpret_cast<const int4*>(&g_csr[p]);
        int4 a0 = __ldg(c4 + 0);
        int4 a1 = __ldg(c4 + 1);
        int4 a2 = __ldg(c4 + 2);
        int4 a3 = __ldg(c4 + 3);
        int cj[16] = { a0.x, a0.y, a0.z, a0.w,
                       a1.x, a1.y, a1.z, a1.w,
                       a2.x, a2.y, a2.z, a2.w,
                       a3.x, a3.y, a3.z, a3.w };
        #pragma unroll
        for (int jp = 0; jp < 8; jp++) {
            uint2 v0 = __ldg(&h2[(size_t)cj[2 * jp]     * 16 + k]);
            uint2 v1 = __ldg(&h2[(size_t)cj[2 * jp + 1] * 16 + k]);
            __half2 s0 = __hadd2(*reinterpret_cast<__half2*>(&v0.x),
                                 *reinterpret_cast<__half2*>(&v1.x));
            __half2 s1 = __hadd2(*reinterpret_cast<__half2*>(&v0.y),
                                 *reinterpret_cast<__half2*>(&v1.y));
            float2 f0 = __half22float2(s0);
            float2 f1 = __half22float2(s1);
            acc.x += f0.x; acc.y += f0.y; acc.z += f1.x; acc.w += f1.y;
        }
        p += 16;
    }
    if (p < end) {   // exactly 8 left (padding guarantees)
        const int4* c4 = reinterpret_cast<const int4*>(&g_csr[p]);
        int4 a0 = __ldg(c4 + 0);
        int4 a1 = __ldg(c4 + 1);
        int cj[8] = { a0.x, a0.y, a0.z, a0.w, a1.x, a1.y, a1.z, a1.w };
        #pragma unroll
        for (int jp = 0; jp < 4; jp++) {
            uint2 v0 = __ldg(&h2[(size_t)cj[2 * jp]     * 16 + k]);
            uint2 v1 = __ldg(&h2[(size_t)cj[2 * jp + 1] * 16 + k]);
            __half2 s0 = __hadd2(*reinterpret_cast<__half2*>(&v0.x),
                                 *reinterpret_cast<__half2*>(&v1.x));
            __half2 s1 = __hadd2(*reinterpret_cast<__half2*>(&v0.y),
                                 *reinterpret_cast<__half2*>(&v1.y));
            float2 f0 = __half22float2(s0);
            float2 f1 = __half22float2(s1);
            acc.x += f0.x; acc.y += f0.y; acc.z += f1.x; acc.w += f1.y;
        }
    }

    float di = g_dinv[i];
    float4 bv = reinterpret_cast<const float4*>(bias)[k];
    acc.x = fmaf(acc.x, di, bv.x);
    acc.y = fmaf(acc.y, di, bv.y);
    acc.z = fmaf(acc.z, di, bv.z);
    acc.w = fmaf(acc.w, di, bv.w);

    if (use_bn) {
        int k4 = k << 2;
        #pragma unroll
        for (int j = 0; j < 4; j++) {
            float a = gam[k4 + j] * rsqrtf(var[k4 + j] + EPS);
            float c = bet[k4 + j] - mu[k4 + j] * a;
            float* f = (&acc.x) + j;
            *f = fmaxf(fmaf(*f, a, c), 0.0f);
        }
    }

    if (out16) {
        __half2 r0 = __floats2half2_rn(acc.x, acc.y);
        __half2 r1 = __floats2half2_rn(acc.z, acc.w);
        uint2 st;
        st.x = *reinterpret_cast<unsigned*>(&r0);
        st.y = *reinterpret_cast<unsigned*>(&r1);
        reinterpret_cast<uint2*>(out16)[(size_t)i * 16 + k] = st;
    }
    if (out32)
        reinterpret_cast<float4*>(out32)[(size_t)i * 16 + k] = acc;
}

// ------------------- launch (forked-graph orchestration) -------------------
extern "C" void kernel_launch(void* const* d_in, const int* in_sizes, int n_in,
                              void* d_out, int out_size)
{
    const float* x   = (const float*)d_in[0];
    const int*   ei  = (const int*)  d_in[1];
    const float* W1  = (const float*)d_in[2];
    const float* b1  = (const float*)d_in[3];
    const float* g1  = (const float*)d_in[4];
    const float* be1 = (const float*)d_in[5];
    const float* m1  = (const float*)d_in[6];
    const float* v1  = (const float*)d_in[7];
    const float* W2  = (const float*)d_in[8];
    const float* b2  = (const float*)d_in[9];
    const float* g2  = (const float*)d_in[10];
    const float* be2 = (const float*)d_in[11];
    const float* m2  = (const float*)d_in[12];
    const float* v2  = (const float*)d_in[13];
    const float* W3  = (const float*)d_in[14];
    const float* b3  = (const float*)d_in[15];

    int N = in_sizes[0] / 64;
    int E = in_sizes[1] / 2;

    const int* row = ei;
    const int* col = ei + E;

    float* out  = (float*)d_out;
    float* emb  = out;                      // global_embeddings [N,64]
    float* pred = out + (size_t)N * 64;     // hc_predictions    [N,64]

    __half *p_h = nullptr, *p_hb = nullptr;
    cudaGetSymbolAddress((void**)&p_h,  g_h);
    cudaGetSymbolAddress((void**)&p_hb, g_hb);

    static cudaStream_t sA = nullptr, sB = nullptr;
    static cudaEvent_t evFork = nullptr, evScan = nullptr, evA = nullptr, evB = nullptr;
    if (sA == nullptr) {
        cudaStreamCreateWithFlags(&sA, cudaStreamNonBlocking);
        cudaStreamCreateWithFlags(&sB, cudaStreamNonBlocking);
        cudaEventCreateWithFlags(&evFork, cudaEventDisableTiming);
        cudaEventCreateWithFlags(&evScan, cudaEventDisableTiming);
        cudaEventCreateWithFlags(&evA,    cudaEventDisableTiming);
        cudaEventCreateWithFlags(&evB,    cudaEventDisableTiming);
    }

    const int T = 256;
    int gN   = (N + T - 1) / T;
    int gV   = ((E >> 2) + 1 + T - 1) / T;   // vectorized edge kernels (+1 tail thread)
    int gN16 = (N * 16 + T - 1) / T;
    int gG   = (N + GEMM_ROWS - 1) / GEMM_ROWS;
    int nb   = (N + SCAN_BLK - 1) / SCAN_BLK;

    // fork: gemm1 (unscaled) starts immediately, overlapping count
    cudaEventRecord(evFork, 0);
    cudaStreamWaitEvent(sB, evFork, 0);
    k_gemm_f32<<<gG, T, 0, sB>>>(x, W1, p_h, N);

    // main chain: count(+rank) -> scan(+dinv) -> build (no atomics)
    k_count  <<<gV, T>>>(row, E);
    k_scan_lb<<<nb, SCAN_BLK>>>(N);
    cudaEventRecord(evScan, 0);
    k_build  <<<gV, T>>>(row, col, E);

    // branch A (after scan): pad padding slots + zero deg/state for next launch
    cudaStreamWaitEvent(sA, evScan, 0);
    k_pad_zero<<<gN, T, 0, sA>>>(N);
    cudaEventRecord(evA, sA);

    // branch B (after scan): apply dinv to gemm1 output
    cudaStreamWaitEvent(sB, evScan, 0);
    k_scale<<<gN16, T, 0, sB>>>(p_h, N);
    cudaEventRecord(evB, sB);

    // join
    cudaStreamWaitEvent(0, evA, 0);
    cudaStreamWaitEvent(0, evB, 0);

    // ---- layer 1: hb = fp16( relu(bn1(agg(h) + b1)) ) ----
    k_pull<<<gN16, T>>>(p_h, b1, p_hb, nullptr, N, g1, be1, m1, v1, 1);

    // ---- layer 2: h = hmma_gemm(hb, W2)*dinv; emb/hb = relu(bn2(agg(h) + b2)) ----
    k_gemm_mma<<<gG, 128>>>(p_hb, W2, p_h, N);
    k_pull<<<gN16, T>>>(p_h, b2, p_hb, emb, N, g2, be2, m2, v2, 1);

    // ---- layer 3: h = hmma_gemm(hb, W3)*dinv; pred = agg(h) + b3 ----
    k_gemm_mma<<<gG, 128>>>(p_hb, W3, p_h, N);
    k_pull<<<gN16, T>>>(p_h, b3, nullptr, pred, N, nullptr, nullptr, nullptr, nullptr, 0);
}